// round 1
// baseline (speedup 1.0000x reference)
#include <cuda_runtime.h>
#include <math.h>

// ---------------- Problem constants ----------------
#define DIM   128
#define E_MAX 100000
#define P_MAX 800000
#define G_MAX 1000
#define TSTEPS 8

// ---------------- Device scratch (no allocations allowed) ----------------
__device__ float d_h  [E_MAX * DIM];        // link_state working copy
__device__ float d_agg[E_MAX * DIM];        // segment-summed messages
__device__ float d_UV [E_MAX * 256];        // [U | V] per edge
__device__ float d_X1 [E_MAX * 384];        // agg @ gru_kernel + b0
__device__ float d_X2 [E_MAX * 384];        // h   @ gru_rec    + b1
__device__ float d_Wuv[128 * 256];          // rearranged W_msg: [K=128, N=256]
__device__ float d_pool[G_MAX * DIM];       // graph pooled states
__device__ float d_r1 [G_MAX * 256];        // readout hidden 1
__device__ float d_r2 [G_MAX * 256];        // readout hidden 2

// ---------------- math helpers ----------------
__device__ __forceinline__ float selu_f(float x) {
    const float sc = 1.0507009873554805f;
    const float al = 1.6732632423543772f;
    return x > 0.f ? sc * x : sc * al * (expf(x) - 1.f);
}
__device__ __forceinline__ float sigmoid_f(float x) {
    return 1.f / (1.f + expf(-x));
}

// ---------------- Rearrange W_msg [256,128] -> Wuv [128,256] ----------------
// Wuv[k][j] = (j<128) ? W_msg[k][j] : W_msg[128+k][j-128]
__global__ void wuv_kernel(const float* __restrict__ Wm, float* __restrict__ Wuv) {
    int i = blockIdx.x * blockDim.x + threadIdx.x;   // over 128*256
    if (i >= 128 * 256) return;
    int k = i >> 8;         // 0..127
    int j = i & 255;        // 0..255
    float v = (j < 128) ? Wm[k * 128 + j] : Wm[(128 + k) * 128 + (j - 128)];
    Wuv[i] = v;
}

// ---------------- Generic SGEMM: C[M,N] = act(A[M,K] @ B[K,N] + bias) ----------------
// Tile 128x128, BK=16, 256 threads, 8x8 per thread. K multiple of 16, N multiple of 128.
#define APAD 4
template<bool HAS_BIAS, bool ACT_SELU>
__global__ void __launch_bounds__(256) sgemm_kernel(
    const float* __restrict__ A, const float* __restrict__ B,
    const float* __restrict__ bias, float* __restrict__ C,
    int M, int N, int K)
{
    __shared__ float As[16][128 + APAD];  // transposed: As[k][row]
    __shared__ float Bs[16][128];         // Bs[k][col]

    const int row0 = blockIdx.x * 128;
    const int col0 = blockIdx.y * 128;
    const int tid = threadIdx.x;
    const int tm = tid >> 4;   // 0..15
    const int tn = tid & 15;   // 0..15

    float acc[8][8];
    #pragma unroll
    for (int i = 0; i < 8; i++)
        #pragma unroll
        for (int j = 0; j < 8; j++) acc[i][j] = 0.f;

    for (int k0 = 0; k0 < K; k0 += 16) {
        // Load A tile: 128 rows x 16 k = 512 float4
        #pragma unroll
        for (int it = 0; it < 2; it++) {
            int fi = tid + it * 256;
            int r  = fi >> 2;     // row in tile
            int kq = fi & 3;      // which float4 along k
            int grow = row0 + r;
            float4 v = make_float4(0.f, 0.f, 0.f, 0.f);
            if (grow < M)
                v = *(const float4*)(A + (size_t)grow * K + k0 + kq * 4);
            As[kq * 4 + 0][r] = v.x;
            As[kq * 4 + 1][r] = v.y;
            As[kq * 4 + 2][r] = v.z;
            As[kq * 4 + 3][r] = v.w;
        }
        // Load B tile: 16 k x 128 cols = 512 float4
        #pragma unroll
        for (int it = 0; it < 2; it++) {
            int fi = tid + it * 256;
            int kr = fi >> 5;     // 0..15
            int cq = fi & 31;     // float4 along cols
            float4 v = *(const float4*)(B + (size_t)(k0 + kr) * N + col0 + cq * 4);
            *(float4*)(&Bs[kr][cq * 4]) = v;
        }
        __syncthreads();

        #pragma unroll
        for (int k = 0; k < 16; k++) {
            float a[8], b[8];
            *(float4*)(a)     = *(const float4*)(&As[k][tm * 8]);
            *(float4*)(a + 4) = *(const float4*)(&As[k][tm * 8 + 4]);
            *(float4*)(b)     = *(const float4*)(&Bs[k][tn * 8]);
            *(float4*)(b + 4) = *(const float4*)(&Bs[k][tn * 8 + 4]);
            #pragma unroll
            for (int i = 0; i < 8; i++)
                #pragma unroll
                for (int j = 0; j < 8; j++)
                    acc[i][j] = fmaf(a[i], b[j], acc[i][j]);
        }
        __syncthreads();
    }

    // Epilogue
    float bcol[8];
    if (HAS_BIAS) {
        #pragma unroll
        for (int j = 0; j < 8; j++) bcol[j] = bias[col0 + tn * 8 + j];
    }
    #pragma unroll
    for (int i = 0; i < 8; i++) {
        int r = row0 + tm * 8 + i;
        if (r >= M) continue;
        #pragma unroll
        for (int j = 0; j < 8; j += 4) {
            float4 v;
            float t0 = acc[i][j + 0], t1 = acc[i][j + 1], t2 = acc[i][j + 2], t3 = acc[i][j + 3];
            if (HAS_BIAS) { t0 += bcol[j]; t1 += bcol[j + 1]; t2 += bcol[j + 2]; t3 += bcol[j + 3]; }
            if (ACT_SELU) { t0 = selu_f(t0); t1 = selu_f(t1); t2 = selu_f(t2); t3 = selu_f(t3); }
            v.x = t0; v.y = t1; v.z = t2; v.w = t3;
            *(float4*)(C + (size_t)r * N + col0 + tn * 8 + j) = v;
        }
    }
}

// ---------------- Message + scatter: agg[second] += selu(U[first]+V[second]+b) ----------------
// one warp per pair, float4 per lane (32 lanes x 4 = 128 dims)
__global__ void msg_kernel(const float* __restrict__ UV, const float* __restrict__ b_msg,
                           const int* __restrict__ first, const int* __restrict__ second,
                           float* __restrict__ agg, int P)
{
    int p = blockIdx.x * 8 + (threadIdx.x >> 5);
    if (p >= P) return;
    int lane = threadIdx.x & 31;
    int f = first[p];
    int s = second[p];
    float4 u = *(const float4*)(UV + (size_t)f * 256 + lane * 4);
    float4 v = *(const float4*)(UV + (size_t)s * 256 + 128 + lane * 4);
    float4 b = *(const float4*)(b_msg + lane * 4);
    float4 m;
    m.x = selu_f(u.x + v.x + b.x);
    m.y = selu_f(u.y + v.y + b.y);
    m.z = selu_f(u.z + v.z + b.z);
    m.w = selu_f(u.w + v.w + b.w);
    float* dst = agg + (size_t)s * 128 + lane * 4;
    asm volatile("red.global.add.v4.f32 [%0], {%1,%2,%3,%4};"
                 :: "l"(dst), "f"(m.x), "f"(m.y), "f"(m.z), "f"(m.w) : "memory");
}

// ---------------- GRU gates (biases already folded into X1/X2) ----------------
__global__ void gates_kernel(const float* __restrict__ X1, const float* __restrict__ X2,
                             float* __restrict__ h, int E)
{
    int i = blockIdx.x * blockDim.x + threadIdx.x;  // over E*32 float4s
    if (i >= E * 32) return;
    int e = i >> 5;
    int q = i & 31;
    size_t b384 = (size_t)e * 384 + q * 4;
    size_t b128 = (size_t)e * 128 + q * 4;
    float4 x1z = *(const float4*)(X1 + b384);
    float4 x1r = *(const float4*)(X1 + b384 + 128);
    float4 x1h = *(const float4*)(X1 + b384 + 256);
    float4 x2z = *(const float4*)(X2 + b384);
    float4 x2r = *(const float4*)(X2 + b384 + 128);
    float4 x2h = *(const float4*)(X2 + b384 + 256);
    float4 hv  = *(const float4*)(h + b128);
    float4 o;
    {
        float z = sigmoid_f(x1z.x + x2z.x);
        float r = sigmoid_f(x1r.x + x2r.x);
        float hh = tanhf(x1h.x + r * x2h.x);
        o.x = z * hv.x + (1.f - z) * hh;
    }
    {
        float z = sigmoid_f(x1z.y + x2z.y);
        float r = sigmoid_f(x1r.y + x2r.y);
        float hh = tanhf(x1h.y + r * x2h.y);
        o.y = z * hv.y + (1.f - z) * hh;
    }
    {
        float z = sigmoid_f(x1z.z + x2z.z);
        float r = sigmoid_f(x1r.z + x2r.z);
        float hh = tanhf(x1h.z + r * x2h.z);
        o.z = z * hv.z + (1.f - z) * hh;
    }
    {
        float z = sigmoid_f(x1z.w + x2z.w);
        float r = sigmoid_f(x1r.w + x2r.w);
        float hh = tanhf(x1h.w + r * x2h.w);
        o.w = z * hv.w + (1.f - z) * hh;
    }
    *(float4*)(h + b128) = o;
}

// ---------------- Graph pooling: pool[gid[e]] += h[e] ----------------
__global__ void pool_kernel(const float* __restrict__ h, const int* __restrict__ gids,
                            float* __restrict__ pool, int E)
{
    int i = blockIdx.x * blockDim.x + threadIdx.x;  // over E*32
    if (i >= E * 32) return;
    int e = i >> 5;
    int q = i & 31;
    int g = gids[e];
    float4 v = *(const float4*)(h + (size_t)e * 128 + q * 4);
    float* dst = pool + (size_t)g * 128 + q * 4;
    asm volatile("red.global.add.v4.f32 [%0], {%1,%2,%3,%4};"
                 :: "l"(dst), "f"(v.x), "f"(v.y), "f"(v.z), "f"(v.w) : "memory");
}

// ---------------- Final readout layer: out[g] = h2[g,:] . W3 + b3 ----------------
__global__ void final_kernel(const float* __restrict__ h2, const float* __restrict__ W3,
                             const float* __restrict__ b3, float* __restrict__ out, int G)
{
    int w = (blockIdx.x * blockDim.x + threadIdx.x) >> 5;
    int lane = threadIdx.x & 31;
    if (w >= G) return;
    float s = 0.f;
    #pragma unroll
    for (int k = 0; k < 8; k++) {
        int j = k * 32 + lane;
        s = fmaf(h2[(size_t)w * 256 + j], W3[j], s);
    }
    #pragma unroll
    for (int off = 16; off > 0; off >>= 1)
        s += __shfl_xor_sync(0xffffffffu, s, off);
    if (lane == 0) out[w] = s + b3[0];
}

// ---------------- Host orchestration ----------------
extern "C" void kernel_launch(void* const* d_in, const int* in_sizes, int n_in,
                              void* d_out, int out_size)
{
    // index shift in case the python-int scalar input is not materialized
    int o = (n_in >= 16) ? 0 : -1;

    const float* link_state = (const float*)d_in[0];
    const int*   gids       = (const int*)d_in[1];
    const int*   first      = (const int*)d_in[2];
    const int*   second     = (const int*)d_in[3];
    const float* W_msg      = (const float*)d_in[5 + o];
    const float* b_msg      = (const float*)d_in[6 + o];
    const float* gru_k      = (const float*)d_in[7 + o];
    const float* gru_rk     = (const float*)d_in[8 + o];
    const float* gru_b      = (const float*)d_in[9 + o];
    const float* W1         = (const float*)d_in[10 + o];
    const float* b1         = (const float*)d_in[11 + o];
    const float* W2         = (const float*)d_in[12 + o];
    const float* b2         = (const float*)d_in[13 + o];
    const float* W3         = (const float*)d_in[14 + o];
    const float* b3         = (const float*)d_in[15 + o];

    const int E = in_sizes[1];
    const int P = in_sizes[2];
    const int G = out_size;

    float *h, *agg, *UV, *X1, *X2, *Wuv, *pool, *r1, *r2;
    cudaGetSymbolAddress((void**)&h,    d_h);
    cudaGetSymbolAddress((void**)&agg,  d_agg);
    cudaGetSymbolAddress((void**)&UV,   d_UV);
    cudaGetSymbolAddress((void**)&X1,   d_X1);
    cudaGetSymbolAddress((void**)&X2,   d_X2);
    cudaGetSymbolAddress((void**)&Wuv,  d_Wuv);
    cudaGetSymbolAddress((void**)&pool, d_pool);
    cudaGetSymbolAddress((void**)&r1,   d_r1);
    cudaGetSymbolAddress((void**)&r2,   d_r2);

    const int mblocks = (E + 127) / 128;

    // init: h = link_state; Wuv from W_msg; UV = h @ Wuv
    cudaMemcpyAsync(h, link_state, (size_t)E * DIM * sizeof(float), cudaMemcpyDeviceToDevice);
    wuv_kernel<<<(128 * 256 + 255) / 256, 256>>>(W_msg, Wuv);
    sgemm_kernel<false, false><<<dim3(mblocks, 2), 256>>>(h, Wuv, nullptr, UV, E, 256, 128);

    for (int t = 0; t < TSTEPS; t++) {
        cudaMemsetAsync(agg, 0, (size_t)E * DIM * sizeof(float));
        msg_kernel<<<(P + 7) / 8, 256>>>(UV, b_msg, first, second, agg, P);
        // X2 = h @ rec_kernel + gru_bias[1]
        sgemm_kernel<true, false><<<dim3(mblocks, 3), 256>>>(h, gru_rk, gru_b + 384, X2, E, 384, 128);
        // X1 = agg @ kernel + gru_bias[0]
        sgemm_kernel<true, false><<<dim3(mblocks, 3), 256>>>(agg, gru_k, gru_b, X1, E, 384, 128);
        gates_kernel<<<(E * 32 + 255) / 256, 256>>>(X1, X2, h, E);
        if (t < TSTEPS - 1)
            sgemm_kernel<false, false><<<dim3(mblocks, 2), 256>>>(h, Wuv, nullptr, UV, E, 256, 128);
    }

    // readout
    cudaMemsetAsync(pool, 0, (size_t)G * DIM * sizeof(float));
    pool_kernel<<<(E * 32 + 255) / 256, 256>>>(h, gids, pool, E);
    const int gblocks = (G + 127) / 128;
    sgemm_kernel<true, true><<<dim3(gblocks, 2), 256>>>(pool, W1, b1, r1, G, 256, 128);
    sgemm_kernel<true, true><<<dim3(gblocks, 2), 256>>>(r1, W2, b2, r2, G, 256, 256);
    final_kernel<<<(G * 32 + 255) / 256, 256>>>(r2, W3, b3, (float*)d_out, G);
}

// round 3
// speedup vs baseline: 1.5875x; 1.5875x over previous
#include <cuda_runtime.h>
#include <cuda_bf16.h>
#include <math.h>
#include <stdint.h>

// ---------------- Problem constants ----------------
#define DIM   128
#define E_MAX 100000
#define P_MAX 800000
#define G_MAX 1000
#define TSTEPS 8

// ---------------- Device scratch (no allocations allowed) ----------------
__device__ float d_h  [E_MAX * DIM];
__device__ float d_agg[E_MAX * DIM];
__device__ float d_UV [E_MAX * 256];
__device__ float d_X1 [E_MAX * 384];
__device__ float d_X2 [E_MAX * 384];
__device__ float d_pool[G_MAX * DIM];
__device__ float d_r1 [G_MAX * 256];
__device__ float d_r2 [G_MAX * 256];
// split+transposed weights: rows 0..383 = gru_kernel^T, 384..767 = gru_rec^T, 768..1023 = Wuv^T
__device__ __nv_bfloat16 d_WtHi[1024 * 128];
__device__ __nv_bfloat16 d_WtLo[1024 * 128];

// ---------------- math helpers ----------------
__device__ __forceinline__ float selu_f(float x) {
    const float sc = 1.0507009873554805f;
    const float al = 1.6732632423543772f;
    return x > 0.f ? sc * x : sc * al * (expf(x) - 1.f);
}
__device__ __forceinline__ float sigmoid_f(float x) { return 1.f / (1.f + expf(-x)); }

__device__ __forceinline__ uint32_t smem_u32(const void* p) {
    uint32_t a;
    asm("{ .reg .u64 t; cvta.to.shared.u64 t, %1; cvt.u32.u64 %0, t; }" : "=r"(a) : "l"(p));
    return a;
}

// swizzled byte offset of 16B chunk c8 (0..15) in row r (256B rows)
__device__ __forceinline__ uint32_t sw_off(int r, int c8) {
    return ((uint32_t)r << 8) + (uint32_t)((c8 ^ (r & 7)) << 4);
}

__device__ __forceinline__ void ldsm_x4(uint32_t addr, uint32_t* r) {
    asm volatile("ldmatrix.sync.aligned.m8n8.x4.shared.b16 {%0,%1,%2,%3}, [%4];"
                 : "=r"(r[0]), "=r"(r[1]), "=r"(r[2]), "=r"(r[3]) : "r"(addr));
}

__device__ __forceinline__ void mma16816(float* c, const uint32_t* a, uint32_t b0, uint32_t b1) {
    asm volatile(
        "mma.sync.aligned.m16n8k16.row.col.f32.bf16.bf16.f32 "
        "{%0,%1,%2,%3}, {%4,%5,%6,%7}, {%8,%9}, {%0,%1,%2,%3};"
        : "+f"(c[0]), "+f"(c[1]), "+f"(c[2]), "+f"(c[3])
        : "r"(a[0]), "r"(a[1]), "r"(a[2]), "r"(a[3]), "r"(b0), "r"(b1));
}

// ---------------- Weight prep: split fp32 weights to (hi,lo) bf16, transposed [N,K] ----------------
__global__ void prep_weights(const float* __restrict__ gru_k, const float* __restrict__ gru_rk,
                             const float* __restrict__ W_msg,
                             __nv_bfloat16* __restrict__ WtHi, __nv_bfloat16* __restrict__ WtLo)
{
    int i = blockIdx.x * blockDim.x + threadIdx.x;
    if (i >= 1024 * 128) return;
    int n = i >> 7;
    int k = i & 127;
    float v;
    if (n < 384) {
        v = gru_k[k * 384 + n];
    } else if (n < 768) {
        v = gru_rk[k * 384 + (n - 384)];
    } else {
        int j = n - 768;
        v = (j < 128) ? W_msg[k * 128 + j] : W_msg[(128 + k) * 128 + (j - 128)];
    }
    __nv_bfloat16 hi = __float2bfloat16(v);
    float lo = v - __bfloat162float(hi);
    WtHi[i] = hi;
    WtLo[i] = __float2bfloat16(lo);
}

// ---------------- Tensor-core GEMM: C[M,Ntot] = A[M,128] @ Wt^T (+bias) ----------------
// bf16x3 split: Ahi*Bhi + Ahi*Blo + Alo*Bhi, fp32 accumulate via mma.sync.m16n8k16.
#define SA_HI 0
#define SA_LO 32768
#define SB_HI 65536
#define SB_LO 98304
#define SMEM_SZ 131072

template<bool HAS_BIAS>
__global__ void __launch_bounds__(256, 1) mma_gemm(
    const float* __restrict__ A, const __nv_bfloat16* __restrict__ BtHi,
    const __nv_bfloat16* __restrict__ BtLo, const float* __restrict__ bias,
    float* __restrict__ C, int M, int Ntot)
{
    extern __shared__ __align__(128) char smem[];
    const uint32_t sb = smem_u32(smem);
    const int tid = threadIdx.x;
    const int row0 = blockIdx.x * 128;
    const int col0 = blockIdx.y * 128;

    // ---- load A tile (fp32) -> split bf16 hi/lo into swizzled SMEM ----
    #pragma unroll
    for (int it = 0; it < 16; it++) {
        int idx = it * 256 + tid;          // over 128 rows x 32 float4
        int r = idx >> 5;
        int c4 = idx & 31;                 // float4 index in row
        int grow = row0 + r;
        float4 v = make_float4(0.f, 0.f, 0.f, 0.f);
        if (grow < M) v = *(const float4*)(A + (size_t)grow * 128 + c4 * 4);
        __nv_bfloat162 h01 = __floats2bfloat162_rn(v.x, v.y);
        __nv_bfloat162 h23 = __floats2bfloat162_rn(v.z, v.w);
        float lx = v.x - __bfloat162float(__low2bfloat16(h01));
        float ly = v.y - __bfloat162float(__high2bfloat16(h01));
        float lz = v.z - __bfloat162float(__low2bfloat16(h23));
        float lw = v.w - __bfloat162float(__high2bfloat16(h23));
        __nv_bfloat162 l01 = __floats2bfloat162_rn(lx, ly);
        __nv_bfloat162 l23 = __floats2bfloat162_rn(lz, lw);
        uint32_t off = ((uint32_t)r << 8) + (uint32_t)((((c4 >> 1) ^ (r & 7)) << 4) | ((c4 & 1) << 3));
        uint2 hu; hu.x = *(uint32_t*)&h01; hu.y = *(uint32_t*)&h23;
        uint2 lu; lu.x = *(uint32_t*)&l01; lu.y = *(uint32_t*)&l23;
        *(uint2*)(smem + SA_HI + off) = hu;
        *(uint2*)(smem + SA_LO + off) = lu;
    }
    // ---- load B tiles (pre-split bf16) into swizzled SMEM ----
    #pragma unroll
    for (int it = 0; it < 16; it++) {
        int idx = it * 256 + tid;          // 0..4095: [hi: 0..2047][lo: 2048..4095]
        int m = idx >> 11;                 // 0=hi, 1=lo (uniform per iteration)
        int ci = idx & 2047;
        int n = ci >> 4;
        int c8 = ci & 15;
        const __nv_bfloat16* src = (m ? BtLo : BtHi) + (size_t)(col0 + n) * 128 + c8 * 8;
        uint4 v = *(const uint4*)src;
        *(uint4*)(smem + (m ? SB_LO : SB_HI) + sw_off(n, c8)) = v;
    }
    __syncthreads();

    const int wid = tid >> 5;
    const int lane = tid & 31;
    const int wr = wid >> 2;       // 0..1 : rows
    const int wc = wid & 3;        // 0..3 : cols
    const int g = lane >> 3;       // ldmatrix group
    const int l8 = lane & 7;

    float acc[4][4][4];
    #pragma unroll
    for (int i = 0; i < 4; i++)
        #pragma unroll
        for (int j = 0; j < 4; j++)
            #pragma unroll
            for (int q = 0; q < 4; q++) acc[i][j][q] = 0.f;

    // per-lane ldmatrix row components
    uint32_t aBase[4], aX[4];
    #pragma unroll
    for (int mt = 0; mt < 4; mt++) {
        int r = wr * 64 + mt * 16 + (g & 1) * 8 + l8;
        aBase[mt] = (uint32_t)r << 8;
        aX[mt] = (uint32_t)(r & 7);
    }
    uint32_t bBase[2], bX[2];
    #pragma unroll
    for (int nt = 0; nt < 2; nt++) {
        int r = wc * 32 + nt * 16 + (g >> 1) * 8 + l8;
        bBase[nt] = (uint32_t)r << 8;
        bX[nt] = (uint32_t)(r & 7);
    }
    const uint32_t aC8 = (uint32_t)(g >> 1);   // A: chunk select within kstep
    const uint32_t bC8 = (uint32_t)(g & 1);    // B: chunk select within kstep

    for (int p = 0; p < 3; p++) {
        const uint32_t Ab = sb + (p == 2 ? SA_LO : SA_HI);
        const uint32_t Bb = sb + (p == 1 ? SB_LO : SB_HI);
        #pragma unroll
        for (int ks = 0; ks < 8; ks++) {
            uint32_t aR[4][4];
            #pragma unroll
            for (int mt = 0; mt < 4; mt++)
                ldsm_x4(Ab + aBase[mt] + ((((uint32_t)(2 * ks) + aC8) ^ aX[mt]) << 4), aR[mt]);
            uint32_t bR[2][4];
            #pragma unroll
            for (int nt = 0; nt < 2; nt++)
                ldsm_x4(Bb + bBase[nt] + ((((uint32_t)(2 * ks) + bC8) ^ bX[nt]) << 4), bR[nt]);
            #pragma unroll
            for (int mt = 0; mt < 4; mt++) {
                #pragma unroll
                for (int j = 0; j < 4; j++) {
                    uint32_t b0 = (j & 1) ? bR[j >> 1][2] : bR[j >> 1][0];
                    uint32_t b1 = (j & 1) ? bR[j >> 1][3] : bR[j >> 1][1];
                    mma16816(acc[mt][j], aR[mt], b0, b1);
                }
            }
        }
    }

    // ---- epilogue ----
    #pragma unroll
    for (int mt = 0; mt < 4; mt++) {
        int r0a = row0 + wr * 64 + mt * 16 + (lane >> 2);
        #pragma unroll
        for (int j = 0; j < 4; j++) {
            int c = col0 + wc * 32 + j * 8 + (lane & 3) * 2;
            float b0 = 0.f, b1 = 0.f;
            if (HAS_BIAS) { b0 = bias[c]; b1 = bias[c + 1]; }
            if (r0a < M) {
                float2 v; v.x = acc[mt][j][0] + b0; v.y = acc[mt][j][1] + b1;
                *(float2*)(C + (size_t)r0a * Ntot + c) = v;
            }
            if (r0a + 8 < M) {
                float2 v; v.x = acc[mt][j][2] + b0; v.y = acc[mt][j][3] + b1;
                *(float2*)(C + (size_t)(r0a + 8) * Ntot + c) = v;
            }
        }
    }
}

// ---------------- FFMA SGEMM (small readout GEMMs) ----------------
#define APAD 4
template<bool HAS_BIAS, bool ACT_SELU>
__global__ void __launch_bounds__(256) sgemm_kernel(
    const float* __restrict__ A, const float* __restrict__ B,
    const float* __restrict__ bias, float* __restrict__ C,
    int M, int N, int K)
{
    __shared__ float As[16][128 + APAD];
    __shared__ float Bs[16][128];

    const int row0 = blockIdx.x * 128;
    const int col0 = blockIdx.y * 128;
    const int tid = threadIdx.x;
    const int tm = tid >> 4;
    const int tn = tid & 15;

    float acc[8][8];
    #pragma unroll
    for (int i = 0; i < 8; i++)
        #pragma unroll
        for (int j = 0; j < 8; j++) acc[i][j] = 0.f;

    for (int k0 = 0; k0 < K; k0 += 16) {
        #pragma unroll
        for (int it = 0; it < 2; it++) {
            int fi = tid + it * 256;
            int r = fi >> 2;
            int kq = fi & 3;
            int grow = row0 + r;
            float4 v = make_float4(0.f, 0.f, 0.f, 0.f);
            if (grow < M)
                v = *(const float4*)(A + (size_t)grow * K + k0 + kq * 4);
            As[kq * 4 + 0][r] = v.x;
            As[kq * 4 + 1][r] = v.y;
            As[kq * 4 + 2][r] = v.z;
            As[kq * 4 + 3][r] = v.w;
        }
        #pragma unroll
        for (int it = 0; it < 2; it++) {
            int fi = tid + it * 256;
            int kr = fi >> 5;
            int cq = fi & 31;
            float4 v = *(const float4*)(B + (size_t)(k0 + kr) * N + col0 + cq * 4);
            *(float4*)(&Bs[kr][cq * 4]) = v;
        }
        __syncthreads();
        #pragma unroll
        for (int k = 0; k < 16; k++) {
            float a[8], b[8];
            *(float4*)(a)     = *(const float4*)(&As[k][tm * 8]);
            *(float4*)(a + 4) = *(const float4*)(&As[k][tm * 8 + 4]);
            *(float4*)(b)     = *(const float4*)(&Bs[k][tn * 8]);
            *(float4*)(b + 4) = *(const float4*)(&Bs[k][tn * 8 + 4]);
            #pragma unroll
            for (int i = 0; i < 8; i++)
                #pragma unroll
                for (int j = 0; j < 8; j++)
                    acc[i][j] = fmaf(a[i], b[j], acc[i][j]);
        }
        __syncthreads();
    }

    float bcol[8];
    if (HAS_BIAS) {
        #pragma unroll
        for (int j = 0; j < 8; j++) bcol[j] = bias[col0 + tn * 8 + j];
    }
    #pragma unroll
    for (int i = 0; i < 8; i++) {
        int r = row0 + tm * 8 + i;
        if (r >= M) continue;
        #pragma unroll
        for (int j = 0; j < 8; j += 4) {
            float4 v;
            float t0 = acc[i][j + 0], t1 = acc[i][j + 1], t2 = acc[i][j + 2], t3 = acc[i][j + 3];
            if (HAS_BIAS) { t0 += bcol[j]; t1 += bcol[j + 1]; t2 += bcol[j + 2]; t3 += bcol[j + 3]; }
            if (ACT_SELU) { t0 = selu_f(t0); t1 = selu_f(t1); t2 = selu_f(t2); t3 = selu_f(t3); }
            v.x = t0; v.y = t1; v.z = t2; v.w = t3;
            *(float4*)(C + (size_t)r * N + col0 + tn * 8 + j) = v;
        }
    }
}

// ---------------- Message + scatter ----------------
__global__ void msg_kernel(const float* __restrict__ UV, const float* __restrict__ b_msg,
                           const int* __restrict__ first, const int* __restrict__ second,
                           float* __restrict__ agg, int P)
{
    int p = blockIdx.x * 8 + (threadIdx.x >> 5);
    if (p >= P) return;
    int lane = threadIdx.x & 31;
    int f = first[p];
    int s = second[p];
    float4 u = *(const float4*)(UV + (size_t)f * 256 + lane * 4);
    float4 v = *(const float4*)(UV + (size_t)s * 256 + 128 + lane * 4);
    float4 b = *(const float4*)(b_msg + lane * 4);
    float4 m;
    m.x = selu_f(u.x + v.x + b.x);
    m.y = selu_f(u.y + v.y + b.y);
    m.z = selu_f(u.z + v.z + b.z);
    m.w = selu_f(u.w + v.w + b.w);
    float* dst = agg + (size_t)s * 128 + lane * 4;
    asm volatile("red.global.add.v4.f32 [%0], {%1,%2,%3,%4};"
                 :: "l"(dst), "f"(m.x), "f"(m.y), "f"(m.z), "f"(m.w) : "memory");
}

// ---------------- GRU gates ----------------
__global__ void gates_kernel(const float* __restrict__ X1, const float* __restrict__ X2,
                             float* __restrict__ h, int E)
{
    int i = blockIdx.x * blockDim.x + threadIdx.x;
    if (i >= E * 32) return;
    int e = i >> 5;
    int q = i & 31;
    size_t b384 = (size_t)e * 384 + q * 4;
    size_t b128 = (size_t)e * 128 + q * 4;
    float4 x1z = *(const float4*)(X1 + b384);
    float4 x1r = *(const float4*)(X1 + b384 + 128);
    float4 x1h = *(const float4*)(X1 + b384 + 256);
    float4 x2z = *(const float4*)(X2 + b384);
    float4 x2r = *(const float4*)(X2 + b384 + 128);
    float4 x2h = *(const float4*)(X2 + b384 + 256);
    float4 hv  = *(const float4*)(h + b128);
    float4 o;
    { float z = sigmoid_f(x1z.x + x2z.x); float r = sigmoid_f(x1r.x + x2r.x);
      float hh = tanhf(x1h.x + r * x2h.x); o.x = z * hv.x + (1.f - z) * hh; }
    { float z = sigmoid_f(x1z.y + x2z.y); float r = sigmoid_f(x1r.y + x2r.y);
      float hh = tanhf(x1h.y + r * x2h.y); o.y = z * hv.y + (1.f - z) * hh; }
    { float z = sigmoid_f(x1z.z + x2z.z); float r = sigmoid_f(x1r.z + x2r.z);
      float hh = tanhf(x1h.z + r * x2h.z); o.z = z * hv.z + (1.f - z) * hh; }
    { float z = sigmoid_f(x1z.w + x2z.w); float r = sigmoid_f(x1r.w + x2r.w);
      float hh = tanhf(x1h.w + r * x2h.w); o.w = z * hv.w + (1.f - z) * hh; }
    *(float4*)(h + b128) = o;
}

// ---------------- Graph pooling ----------------
__global__ void pool_kernel(const float* __restrict__ h, const int* __restrict__ gids,
                            float* __restrict__ pool, int E)
{
    int i = blockIdx.x * blockDim.x + threadIdx.x;
    if (i >= E * 32) return;
    int e = i >> 5;
    int q = i & 31;
    int g = gids[e];
    float4 v = *(const float4*)(h + (size_t)e * 128 + q * 4);
    float* dst = pool + (size_t)g * 128 + q * 4;
    asm volatile("red.global.add.v4.f32 [%0], {%1,%2,%3,%4};"
                 :: "l"(dst), "f"(v.x), "f"(v.y), "f"(v.z), "f"(v.w) : "memory");
}

// ---------------- Final readout ----------------
__global__ void final_kernel(const float* __restrict__ h2, const float* __restrict__ W3,
                             const float* __restrict__ b3, float* __restrict__ out, int G)
{
    int w = (blockIdx.x * blockDim.x + threadIdx.x) >> 5;
    int lane = threadIdx.x & 31;
    if (w >= G) return;
    float s = 0.f;
    #pragma unroll
    for (int k = 0; k < 8; k++) {
        int j = k * 32 + lane;
        s = fmaf(h2[(size_t)w * 256 + j], W3[j], s);
    }
    #pragma unroll
    for (int off = 16; off > 0; off >>= 1)
        s += __shfl_xor_sync(0xffffffffu, s, off);
    if (lane == 0) out[w] = s + b3[0];
}

// ---------------- Host orchestration ----------------
extern "C" void kernel_launch(void* const* d_in, const int* in_sizes, int n_in,
                              void* d_out, int out_size)
{
    int o = (n_in >= 16) ? 0 : -1;

    const float* link_state = (const float*)d_in[0];
    const int*   gids       = (const int*)d_in[1];
    const int*   first      = (const int*)d_in[2];
    const int*   second     = (const int*)d_in[3];
    const float* W_msg      = (const float*)d_in[5 + o];
    const float* b_msg      = (const float*)d_in[6 + o];
    const float* gru_k      = (const float*)d_in[7 + o];
    const float* gru_rk     = (const float*)d_in[8 + o];
    const float* gru_b      = (const float*)d_in[9 + o];
    const float* W1         = (const float*)d_in[10 + o];
    const float* b1         = (const float*)d_in[11 + o];
    const float* W2         = (const float*)d_in[12 + o];
    const float* b2         = (const float*)d_in[13 + o];
    const float* W3         = (const float*)d_in[14 + o];
    const float* b3         = (const float*)d_in[15 + o];

    const int E = in_sizes[1];
    const int P = in_sizes[2];
    const int G = out_size;

    float *h, *agg, *UV, *X1, *X2, *pool, *r1, *r2;
    __nv_bfloat16 *WtHi, *WtLo;
    cudaGetSymbolAddress((void**)&h,    d_h);
    cudaGetSymbolAddress((void**)&agg,  d_agg);
    cudaGetSymbolAddress((void**)&UV,   d_UV);
    cudaGetSymbolAddress((void**)&X1,   d_X1);
    cudaGetSymbolAddress((void**)&X2,   d_X2);
    cudaGetSymbolAddress((void**)&pool, d_pool);
    cudaGetSymbolAddress((void**)&r1,   d_r1);
    cudaGetSymbolAddress((void**)&r2,   d_r2);
    cudaGetSymbolAddress((void**)&WtHi, d_WtHi);
    cudaGetSymbolAddress((void**)&WtLo, d_WtLo);

    cudaFuncSetAttribute(mma_gemm<true>,  cudaFuncAttributeMaxDynamicSharedMemorySize, SMEM_SZ);
    cudaFuncSetAttribute(mma_gemm<false>, cudaFuncAttributeMaxDynamicSharedMemorySize, SMEM_SZ);

    const __nv_bfloat16* WkHi  = WtHi;              const __nv_bfloat16* WkLo  = WtLo;
    const __nv_bfloat16* WrkHi = WtHi + 384 * 128;  const __nv_bfloat16* WrkLo = WtLo + 384 * 128;
    const __nv_bfloat16* WuvHi = WtHi + 768 * 128;  const __nv_bfloat16* WuvLo = WtLo + 768 * 128;

    const int mblocks = (E + 127) / 128;

    prep_weights<<<(1024 * 128 + 255) / 256, 256>>>(gru_k, gru_rk, W_msg, WtHi, WtLo);
    cudaMemcpyAsync(h, link_state, (size_t)E * DIM * sizeof(float), cudaMemcpyDeviceToDevice);
    mma_gemm<false><<<dim3(mblocks, 2), 256, SMEM_SZ>>>(h, WuvHi, WuvLo, nullptr, UV, E, 256);

    for (int t = 0; t < TSTEPS; t++) {
        cudaMemsetAsync(agg, 0, (size_t)E * DIM * sizeof(float));
        msg_kernel<<<(P + 7) / 8, 256>>>(UV, b_msg, first, second, agg, P);
        mma_gemm<true><<<dim3(mblocks, 3), 256, SMEM_SZ>>>(h, WrkHi, WrkLo, gru_b + 384, X2, E, 384);
        mma_gemm<true><<<dim3(mblocks, 3), 256, SMEM_SZ>>>(agg, WkHi, WkLo, gru_b, X1, E, 384);
        gates_kernel<<<(E * 32 + 255) / 256, 256>>>(X1, X2, h, E);
        if (t < TSTEPS - 1)
            mma_gemm<false><<<dim3(mblocks, 2), 256, SMEM_SZ>>>(h, WuvHi, WuvLo, nullptr, UV, E, 256);
    }

    cudaMemsetAsync(pool, 0, (size_t)G * DIM * sizeof(float));
    pool_kernel<<<(E * 32 + 255) / 256, 256>>>(h, gids, pool, E);
    const int gblocks = (G + 127) / 128;
    sgemm_kernel<true, true><<<dim3(gblocks, 2), 256>>>(pool, W1, b1, r1, G, 256, 128);
    sgemm_kernel<true, true><<<dim3(gblocks, 2), 256>>>(r1, W2, b2, r2, G, 256, 256);
    final_kernel<<<(G * 32 + 255) / 256, 256>>>(r2, W3, b3, (float*)d_out, G);
}